// round 2
// baseline (speedup 1.0000x reference)
#include <cuda_runtime.h>
#include <cstdint>

#define B_DIM 16
#define M_DIM 2048
#define F_IN  128
#define F_OUT 64
#define ALPHA 0.2f

// Scratch (allocation-free rule: __device__ globals)
__device__ float g_Wh[(size_t)B_DIM * M_DIM * F_OUT];   // 8 MB
__device__ float g_r[(size_t)B_DIM * M_DIM];            // exp((a-1)*f1)
__device__ float g_E2[(size_t)B_DIM * M_DIM];           // exp(f2)
__device__ float g_E2a[(size_t)B_DIM * M_DIM];          // exp(a*f2)

// ---------------------------------------------------------------------------
// Kernel 1: Wh = h @ W  (per row), f1 = Wh@a1, f2 = Wh@a2, then the
// separable-exp precomputes. 4 rows per 256-thread CTA.
// ---------------------------------------------------------------------------
__global__ __launch_bounds__(256) void k_wh(const float* __restrict__ h,
                                            const float* __restrict__ W,
                                            const float* __restrict__ a) {
    __shared__ float hs[4][F_IN];
    __shared__ float whs[4][F_OUT];
    const int tid = threadIdx.x;
    const int rr = tid >> 6;          // 0..3 row within CTA
    const int c  = tid & 63;          // 0..63 output col
    const size_t row0 = (size_t)blockIdx.x * 4;

    // cooperative load of 4 h rows (512 floats) as float2
    ((float2*)&hs[0][0])[tid] = ((const float2*)(h + row0 * F_IN))[tid];
    __syncthreads();

    float acc = 0.f;
#pragma unroll 8
    for (int k = 0; k < F_IN; ++k)
        acc += hs[rr][k] * W[k * F_OUT + c];

    const size_t row = row0 + rr;
    g_Wh[row * F_OUT + c] = acc;
    whs[rr][c] = acc;
    __syncthreads();

    if (c < 2) {
        float f = 0.f;
#pragma unroll 8
        for (int k = 0; k < F_OUT; ++k)
            f += whs[rr][k] * a[c * F_OUT + k];
        if (c == 0) {
            g_r[row] = expf((ALPHA - 1.0f) * f);   // exp(-0.8*f1)
        } else {
            g_E2[row]  = expf(f);                  // exp(f2)
            g_E2a[row] = expf(ALPHA * f);          // exp(0.2*f2)
        }
    }
}

// ---------------------------------------------------------------------------
// Kernel 2: fused masked-softmax + attn@Wh + elu.
// Grid (32, 16): CTA = (row block of 64) x (batch). 256 threads.
// Sweep j in 16 blocks of 128:
//   stage 1: p[i][j] = adj ? max(E2[j], r[i]*E2a[j]) : 0  -> smem (+ row sums)
//   stage 2: acc[i][c] += p[i][j] * Whs[j][c]  (register-tiled SGEMM)
// Epilogue: out = elu(acc / rowsum).
// ---------------------------------------------------------------------------
#define BI 64
#define BJ 128
#define PSTR 132                     // padded p stride (floats), mult of 4
#define SM_WHS 0                     // 128*64 = 8192 floats
#define SM_PS  8192                  // 64*132 = 8448 floats
#define SM_RS  (8192 + 8448)         // 64 floats
#define SM_LS  (SM_RS + 64)          // 64 floats
#define SMEM2_BYTES ((SM_LS + 64) * 4)

__global__ __launch_bounds__(256, 3) void k_gat(const int* __restrict__ adj,
                                                float* __restrict__ out) {
    extern __shared__ float sm[];
    float* Whs = sm + SM_WHS;
    float* ps  = sm + SM_PS;
    float* rs  = sm + SM_RS;
    float* ls  = sm + SM_LS;

    const int tid = threadIdx.x;
    const int b   = blockIdx.y;
    const int i0  = blockIdx.x * BI;
    const size_t brow = (size_t)b * M_DIM;

    if (tid < BI) {
        rs[tid] = g_r[brow + i0 + tid];
        ls[tid] = 0.f;
    }
    __syncthreads();

    const int lane = tid & 31;
    const int w    = tid >> 5;           // warp 0..7
    // stage-2 mapping: ct in the slow index so Wh loads are broadcast-clean
    const int jh  = tid >> 7;            // 0..1 (j half)
    const int rem = tid & 127;
    const int ct  = rem >> 4;            // 0..7 -> c0 = 8*ct
    const int it  = rem & 15;            // 0..15 -> i0t = 4*it
    const int i0t = it * 4;
    const int c0  = ct * 8;

    float acc[4][8];
#pragma unroll
    for (int ii = 0; ii < 4; ++ii)
#pragma unroll
        for (int cc = 0; cc < 8; ++cc) acc[ii][cc] = 0.f;

    for (int jb = 0; jb < M_DIM / BJ; ++jb) {
        const int j0 = jb * BJ;

        // --- load Wh tile (128x64 f32 = 32KB) ---
        {
            const float4* src = (const float4*)(g_Wh + (brow + j0) * F_OUT);
            float4* dst = (float4*)Whs;
#pragma unroll
            for (int kk = 0; kk < 8; ++kk)
                dst[tid + 256 * kk] = src[tid + 256 * kk];
        }

        // per-lane column factors (L1-resident across the 8 warps)
        const float4 e2  = *(const float4*)(g_E2  + brow + j0 + lane * 4);
        const float4 e2a = *(const float4*)(g_E2a + brow + j0 + lane * 4);

        // --- stage 1: scores -> p tile + row sums ---
#pragma unroll
        for (int ii = 0; ii < 8; ++ii) {
            const int i = ii * 8 + w;
            const float rr = rs[i];
            const int4 av = *(const int4*)(adj + (brow + i0 + i) * (size_t)M_DIM
                                               + j0 + lane * 4);
            float p0 = fmaxf(e2.x, rr * e2a.x) * __int_as_float(av.x * 0x3F800000);
            float p1 = fmaxf(e2.y, rr * e2a.y) * __int_as_float(av.y * 0x3F800000);
            float p2 = fmaxf(e2.z, rr * e2a.z) * __int_as_float(av.z * 0x3F800000);
            float p3 = fmaxf(e2.w, rr * e2a.w) * __int_as_float(av.w * 0x3F800000);
            *(float4*)&ps[i * PSTR + lane * 4] = make_float4(p0, p1, p2, p3);
            float s = (p0 + p1) + (p2 + p3);
            s += __shfl_xor_sync(0xffffffffu, s, 16);
            s += __shfl_xor_sync(0xffffffffu, s, 8);
            s += __shfl_xor_sync(0xffffffffu, s, 4);
            s += __shfl_xor_sync(0xffffffffu, s, 2);
            s += __shfl_xor_sync(0xffffffffu, s, 1);
            if (lane == 0) ls[i] += s;
        }
        __syncthreads();

        // --- stage 2: acc += p @ Whs (this thread: 4 rows x 8 cols, 64 j) ---
        const int jbase = jh * 64;
#pragma unroll 1
        for (int jj = 0; jj < 64; jj += 4) {
            float4 pr[4];
#pragma unroll
            for (int ii = 0; ii < 4; ++ii)
                pr[ii] = *(const float4*)&ps[(i0t + ii) * PSTR + jbase + jj];
#pragma unroll
            for (int u = 0; u < 4; ++u) {
                const float* wrow = &Whs[(jbase + jj + u) * F_OUT + c0];
                const float4 wA = *(const float4*)wrow;
                const float4 wB = *(const float4*)(wrow + 4);
#pragma unroll
                for (int ii = 0; ii < 4; ++ii) {
                    const float p = (u == 0) ? pr[ii].x :
                                    (u == 1) ? pr[ii].y :
                                    (u == 2) ? pr[ii].z : pr[ii].w;
                    acc[ii][0] += p * wA.x;
                    acc[ii][1] += p * wA.y;
                    acc[ii][2] += p * wA.z;
                    acc[ii][3] += p * wA.w;
                    acc[ii][4] += p * wB.x;
                    acc[ii][5] += p * wB.y;
                    acc[ii][6] += p * wB.z;
                    acc[ii][7] += p * wB.w;
                }
            }
        }
        __syncthreads();
    }

    // --- epilogue: merge j-halves, normalize, elu, store ---
    float* accbuf = sm;   // reuse Whs region (8192 floats = 2 * 64*64)
#pragma unroll
    for (int ii = 0; ii < 4; ++ii) {
        float* dstp = &accbuf[jh * 4096 + (i0t + ii) * F_OUT + c0];
        *(float4*)dstp       = make_float4(acc[ii][0], acc[ii][1], acc[ii][2], acc[ii][3]);
        *(float4*)(dstp + 4) = make_float4(acc[ii][4], acc[ii][5], acc[ii][6], acc[ii][7]);
    }
    __syncthreads();
#pragma unroll
    for (int k = 0; k < 16; ++k) {
        const int e = tid + 256 * k;          // 0..4095
        const int i = e >> 6;
        const int c = e & 63;
        float v = (accbuf[e] + accbuf[4096 + e]) / ls[i];
        v = (v > 0.f) ? v : (expf(v) - 1.0f);
        out[(brow + i0 + i) * F_OUT + c] = v;
    }
}

// ---------------------------------------------------------------------------
extern "C" void kernel_launch(void* const* d_in, const int* in_sizes, int n_in,
                              void* d_out, int out_size) {
    const float* h   = (const float*)d_in[0];
    const int*   adj = (const int*)d_in[1];
    const float* W   = (const float*)d_in[2];
    const float* a   = (const float*)d_in[3];
    float* out = (float*)d_out;

    (void)in_sizes; (void)n_in; (void)out_size;

    cudaFuncSetAttribute(k_gat, cudaFuncAttributeMaxDynamicSharedMemorySize,
                         SMEM2_BYTES);

    k_wh<<<(B_DIM * M_DIM) / 4, 256>>>(h, W, a);

    dim3 grid2(M_DIM / BI, B_DIM);
    k_gat<<<grid2, 256, SMEM2_BYTES>>>(adj, out);
}

// round 4
// speedup vs baseline: 1.4810x; 1.4810x over previous
#include <cuda_runtime.h>
#include <cstdint>

#define B_DIM 16
#define M_DIM 2048
#define F_IN  128
#define F_OUT 64
#define ALPHA 0.2f

// Scratch (allocation-free rule: __device__ globals)
__device__ float g_Wh[(size_t)B_DIM * M_DIM * F_OUT];   // 8 MB
__device__ float g_r[(size_t)B_DIM * M_DIM];            // exp((a-1)*f1)
__device__ float g_E2[(size_t)B_DIM * M_DIM];           // exp(f2)
__device__ float g_E2a[(size_t)B_DIM * M_DIM];          // exp(a*f2)

// packed f32x2 FMA (sm_103a FFMA2 — only reachable via PTX)
#define FFMA2(acc, a, b) \
    asm("fma.rn.f32x2 %0, %1, %2, %0;" : "+l"(acc) : "l"(a), "l"(b))

// ---------------------------------------------------------------------------
// Kernel 1: Wh = h @ W, f1/f2 dots, separable-exp precomputes.
// 16 rows per 512-thread CTA; W staged in smem (cuts W L2 traffic 4x and
// kills the LDG-latency chain that made v1 take 60us).
// ---------------------------------------------------------------------------
__global__ __launch_bounds__(512) void k_wh(const float* __restrict__ h,
                                            const float* __restrict__ W,
                                            const float* __restrict__ a) {
    __shared__ float Ws[F_IN * F_OUT];   // 32 KB
    __shared__ float hs[16][F_IN];       // 8 KB
    __shared__ float whs[16][F_OUT];     // 4 KB
    const int tid = threadIdx.x;
    const size_t row0 = (size_t)blockIdx.x * 16;

    // cooperative loads: W (8192 floats), h rows (2048 floats)
    {
        const float4* ws = (const float4*)W;
        float4* wd = (float4*)Ws;
#pragma unroll
        for (int k = 0; k < 4; ++k) wd[tid + 512 * k] = ws[tid + 512 * k];
        ((float4*)&hs[0][0])[tid] = ((const float4*)(h + row0 * F_IN))[tid];
    }
    __syncthreads();

    const int c  = tid & 63;          // output col
    const int r0 = tid >> 6;          // 0..7 ; rows r0 and r0+8
    float acc0 = 0.f, acc1 = 0.f;
#pragma unroll 8
    for (int k = 0; k < F_IN; ++k) {
        const float wv = Ws[k * F_OUT + c];
        acc0 += hs[r0][k] * wv;
        acc1 += hs[r0 + 8][k] * wv;
    }
    g_Wh[(row0 + r0) * F_OUT + c]     = acc0;
    g_Wh[(row0 + r0 + 8) * F_OUT + c] = acc1;
    whs[r0][c]     = acc0;
    whs[r0 + 8][c] = acc1;
    __syncthreads();

    // f1/f2 per row; 32 threads, each one (row, which) dot of length 64
    if (tid < 32) {
        const int row   = tid >> 1;
        const int which = tid & 1;
        float f = 0.f;
#pragma unroll 8
        for (int k = 0; k < F_OUT; ++k)
            f += whs[row][k] * a[which * F_OUT + k];
        const size_t grow = row0 + row;
        if (which == 0) {
            g_r[grow] = expf((ALPHA - 1.0f) * f);
        } else {
            g_E2[grow]  = expf(f);
            g_E2a[grow] = expf(ALPHA * f);
        }
    }
}

// ---------------------------------------------------------------------------
// Kernel 2: fused masked-softmax + attn@Wh + elu.
// Grid (32, 16). 256 threads. j swept in 16 blocks of 128.
// p tile stored with a 16B-group XOR swizzle so stage-2 row-strided loads are
// conflict-free (2 wavefronts, down from 8). Stage-2 GEMM uses packed
// fma.rn.f32x2 over c-pairs: Wh pairs loaded directly as ulonglong2.
// ---------------------------------------------------------------------------
#define BI 64
#define BJ 128
#define SM_WHS 0                       // 128*64 = 8192 floats
#define SM_PS  8192                    // 64*128 = 8192 floats (swizzled)
#define SM_RS  (8192 + 8192)
#define SM_LS  (SM_RS + 64)
#define SMEM2_BYTES ((SM_LS + 64) * 4)

// swizzled index into the 64x128 p tile: row = 512B, 16B groups XORed by
// (i>>2)&7 so lanes differing by 4 rows hit distinct bank groups.
__device__ __forceinline__ int ps_idx(int i, int j) {
    const int q  = j >> 2;
    const int qs = q ^ ((i >> 2) & 7);
    return i * 128 + qs * 4 + (j & 3);
}

__global__ __launch_bounds__(256, 3) void k_gat(const int* __restrict__ adj,
                                                float* __restrict__ out) {
    extern __shared__ float sm[];
    float* Whs = sm + SM_WHS;
    float* ps  = sm + SM_PS;
    float* rs  = sm + SM_RS;
    float* ls  = sm + SM_LS;

    const int tid = threadIdx.x;
    const int b   = blockIdx.y;
    const int i0  = blockIdx.x * BI;
    const size_t brow = (size_t)b * M_DIM;

    if (tid < BI) {
        rs[tid] = g_r[brow + i0 + tid];
        ls[tid] = 0.f;
    }
    __syncthreads();

    const int lane = tid & 31;
    const int w    = tid >> 5;           // warp 0..7
    // stage-2 mapping: ct slow so Wh LDS.128s broadcast (2 addrs/warp)
    const int jh  = tid >> 7;            // 0..1 (j half)
    const int rem = tid & 127;
    const int ct  = rem >> 4;            // 0..7 -> c0 = 8*ct
    const int it  = rem & 15;            // 0..15 -> i0t = 4*it
    const int i0t = it * 4;
    const int c0  = ct * 8;

    unsigned long long acc2[4][4];       // 4 rows x 4 c-pairs (f32x2)
#pragma unroll
    for (int ii = 0; ii < 4; ++ii)
#pragma unroll
        for (int cc = 0; cc < 4; ++cc) acc2[ii][cc] = 0ull;

    for (int jb = 0; jb < M_DIM / BJ; ++jb) {
        const int j0 = jb * BJ;

        // --- load Wh tile (128x64 f32 = 32KB) ---
        {
            const float4* src = (const float4*)(g_Wh + (brow + j0) * F_OUT);
            float4* dst = (float4*)Whs;
#pragma unroll
            for (int kk = 0; kk < 8; ++kk)
                dst[tid + 256 * kk] = src[tid + 256 * kk];
        }

        const float4 e2  = *(const float4*)(g_E2  + brow + j0 + lane * 4);
        const float4 e2a = *(const float4*)(g_E2a + brow + j0 + lane * 4);

        // --- stage 1: scores -> swizzled p tile + row sums ---
#pragma unroll
        for (int ii = 0; ii < 8; ++ii) {
            const int i = ii * 8 + w;
            const float rr = rs[i];
            const int4 av = *(const int4*)(adj + (brow + i0 + i) * (size_t)M_DIM
                                               + j0 + lane * 4);
            float p0 = fmaxf(e2.x, rr * e2a.x) * __int_as_float(av.x * 0x3F800000);
            float p1 = fmaxf(e2.y, rr * e2a.y) * __int_as_float(av.y * 0x3F800000);
            float p2 = fmaxf(e2.z, rr * e2a.z) * __int_as_float(av.z * 0x3F800000);
            float p3 = fmaxf(e2.w, rr * e2a.w) * __int_as_float(av.w * 0x3F800000);
            *(float4*)&ps[ps_idx(i, lane * 4)] = make_float4(p0, p1, p2, p3);
            float s = (p0 + p1) + (p2 + p3);
            s += __shfl_xor_sync(0xffffffffu, s, 16);
            s += __shfl_xor_sync(0xffffffffu, s, 8);
            s += __shfl_xor_sync(0xffffffffu, s, 4);
            s += __shfl_xor_sync(0xffffffffu, s, 2);
            s += __shfl_xor_sync(0xffffffffu, s, 1);
            if (lane == 0) ls[i] += s;
        }
        __syncthreads();

        // --- stage 2: acc += p @ Whs, f32x2-packed (4 rows x 8 cols, 64 j) ---
        const int jbase = jh * 64;
#pragma unroll 1
        for (int jj = 0; jj < 64; jj += 4) {
            float4 pr[4];
#pragma unroll
            for (int ii = 0; ii < 4; ++ii)
                pr[ii] = *(const float4*)&ps[ps_idx(i0t + ii, jbase + jj)];
#pragma unroll
            for (int u = 0; u < 4; ++u) {
                const float* wrow = &Whs[(jbase + jj + u) * F_OUT + c0];
                const ulonglong2 wv0 = *(const ulonglong2*)wrow;       // c0..c3
                const ulonglong2 wv1 = *(const ulonglong2*)(wrow + 4); // c4..c7
#pragma unroll
                for (int ii = 0; ii < 4; ++ii) {
                    const float p = (u == 0) ? pr[ii].x :
                                    (u == 1) ? pr[ii].y :
                                    (u == 2) ? pr[ii].z : pr[ii].w;
                    unsigned long long pp;
                    asm("mov.b64 %0, {%1, %1};" : "=l"(pp)
                        : "r"(__float_as_uint(p)));
                    FFMA2(acc2[ii][0], pp, wv0.x);
                    FFMA2(acc2[ii][1], pp, wv0.y);
                    FFMA2(acc2[ii][2], pp, wv1.x);
                    FFMA2(acc2[ii][3], pp, wv1.y);
                }
            }
        }
        __syncthreads();
    }

    // --- epilogue: merge j-halves, normalize, elu, store ---
    float* accbuf = sm;   // reuse Whs region (8192 floats = 2 * 64*64)
#pragma unroll
    for (int ii = 0; ii < 4; ++ii) {
        float* dstp = &accbuf[jh * 4096 + (i0t + ii) * F_OUT + c0];
#pragma unroll
        for (int cc = 0; cc < 4; ++cc) {
            const unsigned long long v = acc2[ii][cc];
            dstp[cc * 2]     = __uint_as_float((unsigned)(v & 0xffffffffull));
            dstp[cc * 2 + 1] = __uint_as_float((unsigned)(v >> 32));
        }
    }
    __syncthreads();
#pragma unroll
    for (int k = 0; k < 16; ++k) {
        const int e = tid + 256 * k;          // 0..4095
        const int i = e >> 6;
        const int c = e & 63;
        float v = (accbuf[e] + accbuf[4096 + e]) / ls[i];
        v = (v > 0.f) ? v : (expf(v) - 1.0f);
        out[(brow + i0 + i) * F_OUT + c] = v;
    }
}

// ---------------------------------------------------------------------------
extern "C" void kernel_launch(void* const* d_in, const int* in_sizes, int n_in,
                              void* d_out, int out_size) {
    const float* h   = (const float*)d_in[0];
    const int*   adj = (const int*)d_in[1];
    const float* W   = (const float*)d_in[2];
    const float* a   = (const float*)d_in[3];
    float* out = (float*)d_out;

    (void)in_sizes; (void)n_in; (void)out_size;

    cudaFuncSetAttribute(k_gat, cudaFuncAttributeMaxDynamicSharedMemorySize,
                         SMEM2_BYTES);

    k_wh<<<(B_DIM * M_DIM) / 16, 512>>>(h, W, a);

    dim3 grid2(M_DIM / BI, B_DIM);
    k_gat<<<grid2, 256, SMEM2_BYTES>>>(adj, out);
}

// round 5
// speedup vs baseline: 1.4903x; 1.0063x over previous
#include <cuda_runtime.h>
#include <cstdint>

#define B_DIM 16
#define M_DIM 2048
#define F_IN  128
#define F_OUT 64
#define ALPHA 0.2f

// Scratch (allocation-free rule: __device__ globals)
__device__ float g_Wh[(size_t)B_DIM * M_DIM * F_OUT];   // 8 MB
__device__ float g_r[(size_t)B_DIM * M_DIM];            // exp((a-1)*f1)
__device__ float g_E2[(size_t)B_DIM * M_DIM];           // exp(f2)
__device__ float g_E2a[(size_t)B_DIM * M_DIM];          // exp(a*f2)

// packed f32x2 FMA (sm_103a FFMA2 — only reachable via PTX)
#define FFMA2(acc, a, b) \
    asm("fma.rn.f32x2 %0, %1, %2, %0;" : "+l"(acc) : "l"(a), "l"(b))

// ---------------------------------------------------------------------------
// Kernel 1: Wh = h @ W, f1/f2 dots, separable-exp precomputes.
// 32 rows per 512-thread CTA; W staged in smem.
// ---------------------------------------------------------------------------
__global__ __launch_bounds__(512) void k_wh(const float* __restrict__ h,
                                            const float* __restrict__ W,
                                            const float* __restrict__ a) {
    __shared__ float Ws[F_IN * F_OUT];   // 32 KB
    __shared__ float hs[32][F_IN];       // 16 KB
    __shared__ float whs[32][F_OUT];     // 8 KB
    const int tid = threadIdx.x;
    const size_t row0 = (size_t)blockIdx.x * 32;

    {
        const float4* ws = (const float4*)W;
        float4* wd = (float4*)Ws;
#pragma unroll
        for (int k = 0; k < 4; ++k) wd[tid + 512 * k] = ws[tid + 512 * k];
        const float4* hsrc = (const float4*)(h + row0 * F_IN);
        float4* hdst = (float4*)&hs[0][0];
        hdst[tid] = hsrc[tid];
        hdst[tid + 512] = hsrc[tid + 512];
    }
    __syncthreads();

    const int c  = tid & 63;          // output col
    const int r0 = tid >> 6;          // 0..7 ; rows r0 + 8k
    float acc0 = 0.f, acc1 = 0.f, acc2_ = 0.f, acc3 = 0.f;
#pragma unroll 8
    for (int k = 0; k < F_IN; ++k) {
        const float wv = Ws[k * F_OUT + c];
        acc0 += hs[r0][k] * wv;
        acc1 += hs[r0 + 8][k] * wv;
        acc2_ += hs[r0 + 16][k] * wv;
        acc3 += hs[r0 + 24][k] * wv;
    }
    g_Wh[(row0 + r0) * F_OUT + c]      = acc0;
    g_Wh[(row0 + r0 + 8) * F_OUT + c]  = acc1;
    g_Wh[(row0 + r0 + 16) * F_OUT + c] = acc2_;
    g_Wh[(row0 + r0 + 24) * F_OUT + c] = acc3;
    whs[r0][c]      = acc0;
    whs[r0 + 8][c]  = acc1;
    whs[r0 + 16][c] = acc2_;
    whs[r0 + 24][c] = acc3;
    __syncthreads();

    // f1/f2 per row; 64 threads, each one (row, which) dot of length 64
    if (tid < 64) {
        const int row   = tid >> 1;
        const int which = tid & 1;
        float f = 0.f;
#pragma unroll 8
        for (int k = 0; k < F_OUT; ++k)
            f += whs[row][k] * a[which * F_OUT + k];
        const size_t grow = row0 + row;
        if (which == 0) {
            g_r[grow] = expf((ALPHA - 1.0f) * f);
        } else {
            g_E2[grow]  = expf(f);
            g_E2a[grow] = expf(ALPHA * f);
        }
    }
}

// ---------------------------------------------------------------------------
// Kernel 2: fused masked-softmax + attn@Wh + elu.
// Grid (32, 16). 256 threads, <=64 regs, ~34KB smem -> occ 4 -> ONE wave.
// j swept in 32 blocks of 64. p tile XOR-swizzled; stage-2 GEMM packed
// fma.rn.f32x2 over c-pairs, thread tile 4i x 8c, j split in halves of 32.
// ---------------------------------------------------------------------------
#define BI 64
#define BJ 64
#define SM_WHS 0                       // 64*64 = 4096 floats
#define SM_PS  4096                    // 64*64 = 4096 floats (swizzled)
#define SM_RS  (4096 + 4096)
#define SM_LS  (SM_RS + 64)
#define SMEM2_BYTES ((SM_LS + 64) * 4)

// swizzled index into the 64x64 p tile (row = 256B): 16B group q=j>>2 (0..15)
// XORed in its low 3 bits by (i>>2)&7.
__device__ __forceinline__ int ps_idx(int i, int j) {
    const int q  = j >> 2;
    const int qs = q ^ ((i >> 2) & 7);
    return i * 64 + qs * 4 + (j & 3);
}

__global__ __launch_bounds__(256, 4) void k_gat(const int* __restrict__ adj,
                                                float* __restrict__ out) {
    extern __shared__ float sm[];
    float* Whs = sm + SM_WHS;
    float* ps  = sm + SM_PS;
    float* rs  = sm + SM_RS;
    float* ls  = sm + SM_LS;

    const int tid = threadIdx.x;
    const int b   = blockIdx.y;
    const int i0  = blockIdx.x * BI;
    const size_t brow = (size_t)b * M_DIM;

    if (tid < BI) {
        rs[tid] = g_r[brow + i0 + tid];
        ls[tid] = 0.f;
    }
    __syncthreads();

    const int lane = tid & 31;
    const int w    = tid >> 5;           // warp 0..7
    // stage-2 mapping: ct slow within warp so Wh loads broadcast
    const int jh  = tid >> 7;            // 0..1 (j half of 32)
    const int rem = tid & 127;
    const int ct  = rem >> 4;            // 0..7 -> c0 = 8*ct
    const int it  = rem & 15;            // 0..15 -> i0t = 4*it
    const int i0t = it * 4;
    const int c0  = ct * 8;

    unsigned long long acc2[4][4];       // 4 rows x 4 c-pairs (f32x2)
#pragma unroll
    for (int ii = 0; ii < 4; ++ii)
#pragma unroll
        for (int cc = 0; cc < 4; ++cc) acc2[ii][cc] = 0ull;

    for (int jb = 0; jb < M_DIM / BJ; ++jb) {
        const int j0 = jb * BJ;

        // --- load Wh tile (64x64 f32 = 16KB) ---
        {
            const float4* src = (const float4*)(g_Wh + (brow + j0) * F_OUT);
            float4* dst = (float4*)Whs;
#pragma unroll
            for (int kk = 0; kk < 4; ++kk)
                dst[tid + 256 * kk] = src[tid + 256 * kk];
        }

        const float2 e2  = *(const float2*)(g_E2  + brow + j0 + lane * 2);
        const float2 e2a = *(const float2*)(g_E2a + brow + j0 + lane * 2);

        // --- stage 1: scores -> swizzled p tile + row sums ---
#pragma unroll
        for (int ii = 0; ii < 8; ++ii) {
            const int i = ii * 8 + w;
            const float rr = rs[i];
            const int2 av = *(const int2*)(adj + (brow + i0 + i) * (size_t)M_DIM
                                               + j0 + lane * 2);
            float p0 = fmaxf(e2.x, rr * e2a.x) * __int_as_float(av.x * 0x3F800000);
            float p1 = fmaxf(e2.y, rr * e2a.y) * __int_as_float(av.y * 0x3F800000);
            *(float2*)&ps[ps_idx(i, lane * 2)] = make_float2(p0, p1);
            float s = p0 + p1;
            s += __shfl_xor_sync(0xffffffffu, s, 16);
            s += __shfl_xor_sync(0xffffffffu, s, 8);
            s += __shfl_xor_sync(0xffffffffu, s, 4);
            s += __shfl_xor_sync(0xffffffffu, s, 2);
            s += __shfl_xor_sync(0xffffffffu, s, 1);
            if (lane == 0) ls[i] += s;
        }
        __syncthreads();

        // --- stage 2: acc += p @ Whs (4 rows x 8 cols, 32 j) ---
        const int jbase = jh * 32;
#pragma unroll 1
        for (int jj = 0; jj < 32; jj += 4) {
            float4 pr[4];
#pragma unroll
            for (int ii = 0; ii < 4; ++ii)
                pr[ii] = *(const float4*)&ps[ps_idx(i0t + ii, jbase + jj)];
#pragma unroll
            for (int u = 0; u < 4; ++u) {
                const float* wrow = &Whs[(jbase + jj + u) * F_OUT + c0];
                const ulonglong2 wv0 = *(const ulonglong2*)wrow;       // c0..c3
                const ulonglong2 wv1 = *(const ulonglong2*)(wrow + 4); // c4..c7
#pragma unroll
                for (int ii = 0; ii < 4; ++ii) {
                    const float p = (u == 0) ? pr[ii].x :
                                    (u == 1) ? pr[ii].y :
                                    (u == 2) ? pr[ii].z : pr[ii].w;
                    unsigned long long pp;
                    asm("mov.b64 %0, {%1, %1};" : "=l"(pp)
                        : "r"(__float_as_uint(p)));
                    FFMA2(acc2[ii][0], pp, wv0.x);
                    FFMA2(acc2[ii][1], pp, wv0.y);
                    FFMA2(acc2[ii][2], pp, wv1.x);
                    FFMA2(acc2[ii][3], pp, wv1.y);
                }
            }
        }
        __syncthreads();
    }

    // --- epilogue: merge j-halves, normalize, elu, store ---
    float* accbuf = sm;   // reuse Whs+ps region (8192 floats = 2 * 64*64)
#pragma unroll
    for (int ii = 0; ii < 4; ++ii) {
        float* dstp = &accbuf[jh * 4096 + (i0t + ii) * F_OUT + c0];
#pragma unroll
        for (int cc = 0; cc < 4; ++cc) {
            const unsigned long long v = acc2[ii][cc];
            dstp[cc * 2]     = __uint_as_float((unsigned)(v & 0xffffffffull));
            dstp[cc * 2 + 1] = __uint_as_float((unsigned)(v >> 32));
        }
    }
    __syncthreads();
#pragma unroll
    for (int k = 0; k < 16; ++k) {
        const int e = tid + 256 * k;          // 0..4095
        const int i = e >> 6;
        const int c = e & 63;
        float v = (accbuf[e] + accbuf[4096 + e]) / ls[i];
        v = (v > 0.f) ? v : (expf(v) - 1.0f);
        out[(brow + i0 + i) * F_OUT + c] = v;
    }
}

// ---------------------------------------------------------------------------
extern "C" void kernel_launch(void* const* d_in, const int* in_sizes, int n_in,
                              void* d_out, int out_size) {
    const float* h   = (const float*)d_in[0];
    const int*   adj = (const int*)d_in[1];
    const float* W   = (const float*)d_in[2];
    const float* a   = (const float*)d_in[3];
    float* out = (float*)d_out;

    (void)in_sizes; (void)n_in; (void)out_size;

    cudaFuncSetAttribute(k_gat, cudaFuncAttributeMaxDynamicSharedMemorySize,
                         SMEM2_BYTES);

    k_wh<<<(B_DIM * M_DIM) / 32, 512>>>(h, W, a);

    dim3 grid2(M_DIM / BI, B_DIM);
    k_gat<<<grid2, 256, SMEM2_BYTES>>>(adj, out);
}

// round 9
// speedup vs baseline: 2.9915x; 2.0073x over previous
#include <cuda_runtime.h>
#include <cuda_bf16.h>
#include <cstdint>

#define B_DIM 16
#define M_DIM 2048
#define F_IN  128
#define F_OUT 64
#define ALPHA 0.2f

// ---------------------------------------------------------------------------
// __device__ scratch (allocation-free rule)
// ---------------------------------------------------------------------------
__device__ float g_r  [(size_t)B_DIM * M_DIM];
__device__ float g_E2 [(size_t)B_DIM * M_DIM];
__device__ float g_E2a[(size_t)B_DIM * M_DIM];
// Wh transposed + bf16 2-term split: [B][F_OUT][M]  (hi + lo)
__device__ __nv_bfloat16 g_WhT_h[(size_t)B_DIM * F_OUT * M_DIM];
__device__ __nv_bfloat16 g_WhT_l[(size_t)B_DIM * F_OUT * M_DIM];

// ---------------------------------------------------------------------------
// helpers
// ---------------------------------------------------------------------------
__device__ __forceinline__ uint32_t smem_u32(const void* p) {
    uint32_t a;
    asm("{ .reg .u64 t; cvta.to.shared.u64 t, %1; cvt.u32.u64 %0, t; }"
        : "=r"(a) : "l"(p));
    return a;
}
// pack two f32 -> bf16x2 (lo 16 bits = a, hi 16 bits = b), round-to-nearest
__device__ __forceinline__ uint32_t pack_bf16(float a, float b) {
    uint32_t r;
    asm("cvt.rn.satfinite.bf16x2.f32 %0, %1, %2;" : "=r"(r) : "f"(b), "f"(a));
    return r;
}
__device__ __forceinline__ void ldsm4(uint32_t* r, uint32_t addr) {
    asm volatile("ldmatrix.sync.aligned.m8n8.x4.shared.b16 {%0,%1,%2,%3}, [%4];"
                 : "=r"(r[0]), "=r"(r[1]), "=r"(r[2]), "=r"(r[3]) : "r"(addr));
}
__device__ __forceinline__ void mma_bf16(float* d, const uint32_t* a,
                                         uint32_t b0, uint32_t b1) {
    asm volatile(
        "mma.sync.aligned.m16n8k16.row.col.f32.bf16.bf16.f32 "
        "{%0,%1,%2,%3}, {%4,%5,%6,%7}, {%8,%9}, {%0,%1,%2,%3};"
        : "+f"(d[0]), "+f"(d[1]), "+f"(d[2]), "+f"(d[3])
        : "r"(a[0]), "r"(a[1]), "r"(a[2]), "r"(a[3]), "r"(b0), "r"(b1));
}

// ---------------------------------------------------------------------------
// Kernel 1: Wh = h @ W ; f1/f2 dots ; separable-exp precomputes ;
// Wh transposed + rn bf16 split -> g_WhT_h / g_WhT_l.  32 rows / 512-thr CTA.
// ---------------------------------------------------------------------------
__global__ __launch_bounds__(512) void k_wh(const float* __restrict__ h,
                                            const float* __restrict__ W,
                                            const float* __restrict__ a) {
    __shared__ float Ws[F_IN * F_OUT];   // 32 KB
    __shared__ float hs[32][F_IN];       // 16 KB
    __shared__ float whs[32][68];        // padded
    const int tid = threadIdx.x;
    const size_t row0 = (size_t)blockIdx.x * 32;
    const int b_    = (int)(row0 >> 11);
    const int jbase = (int)(row0 & 2047);

    {
        const float4* ws = (const float4*)W;
        float4* wd = (float4*)Ws;
#pragma unroll
        for (int k = 0; k < 4; ++k) wd[tid + 512 * k] = ws[tid + 512 * k];
        const float4* hsrc = (const float4*)(h + row0 * F_IN);
        float4* hdst = (float4*)&hs[0][0];
        hdst[tid] = hsrc[tid];
        hdst[tid + 512] = hsrc[tid + 512];
    }
    __syncthreads();

    const int c  = tid & 63;
    const int r0 = tid >> 6;             // rows r0 + 8k
    float acc0 = 0.f, acc1 = 0.f, acc2_ = 0.f, acc3 = 0.f;
#pragma unroll 8
    for (int k = 0; k < F_IN; ++k) {
        const float wv = Ws[k * F_OUT + c];
        acc0  += hs[r0][k] * wv;
        acc1  += hs[r0 + 8][k] * wv;
        acc2_ += hs[r0 + 16][k] * wv;
        acc3  += hs[r0 + 24][k] * wv;
    }
    whs[r0][c]      = acc0;
    whs[r0 + 8][c]  = acc1;
    whs[r0 + 16][c] = acc2_;
    whs[r0 + 24][c] = acc3;
    __syncthreads();

    // transposed bf16 split store: thread -> (c = tid>>3, 4 rows at (tid&7)*4)
    {
        const int cc = tid >> 3;
        const int rq = tid & 7;
        const float x0 = whs[rq * 4 + 0][cc];
        const float x1 = whs[rq * 4 + 1][cc];
        const float x2 = whs[rq * 4 + 2][cc];
        const float x3 = whs[rq * 4 + 3][cc];
        const uint32_t h01 = pack_bf16(x0, x1);
        const uint32_t h23 = pack_bf16(x2, x3);
        const float l0 = x0 - __uint_as_float(h01 << 16);
        const float l1 = x1 - __uint_as_float(h01 & 0xFFFF0000u);
        const float l2 = x2 - __uint_as_float(h23 << 16);
        const float l3 = x3 - __uint_as_float(h23 & 0xFFFF0000u);
        const uint32_t q01 = pack_bf16(l0, l1);
        const uint32_t q23 = pack_bf16(l2, l3);
        const size_t idx = ((size_t)b_ * F_OUT + cc) * M_DIM + jbase + rq * 4;
        *(uint2*)(g_WhT_h + idx) = make_uint2(h01, h23);
        *(uint2*)(g_WhT_l + idx) = make_uint2(q01, q23);
    }

    // f1/f2 per row
    if (tid < 64) {
        const int row   = tid >> 1;
        const int which = tid & 1;
        float f = 0.f;
#pragma unroll 8
        for (int k = 0; k < F_OUT; ++k)
            f += whs[row][k] * a[which * F_OUT + k];
        const size_t grow = row0 + row;
        if (which == 0) {
            g_r[grow] = expf((ALPHA - 1.0f) * f);
        } else {
            g_E2[grow]  = expf(f);
            g_E2a[grow] = expf(ALPHA * f);
        }
    }
}

// ---------------------------------------------------------------------------
// Kernel 2: fused masked-softmax + attn@Wh (mma.sync bf16-split) + elu.
// Grid (16,16): CTA = 128 rows x batch. 512 threads = 16 warps (4m x 4n,
// warp tile 32x16). occ 2 -> one wave.
// Per jb (128 j): stage-1 warp-per-row computes p -> split bf16 A tiles
// (272B pitch, conflict-free); B split tiles staged from g_WhT; MMA loop:
// 8 k-steps x (6 ldmatrix.x4 + 12 HMMA)  [terms hh, hl, lh].
// ---------------------------------------------------------------------------
#define BI 128
#define BJ 128
#define APITCH 272               // bytes per tile row (136 bf16, 17 x 16B)
#define SA_H 0                   // 128 x 272 = 34816
#define SA_L 34816
#define SB_H 69632               // 64 x 272 = 17408
#define SB_L 87040
#define SLS  104448              // 128 f32 row sums
#define SMEM_TOTAL 104960

__global__ __launch_bounds__(512, 2) void k_gat(const int* __restrict__ adj,
                                                float* __restrict__ out) {
    extern __shared__ char smem[];
    const uint32_t sbase = smem_u32(smem);
    float* ls = (float*)(smem + SLS);

    const int tid  = threadIdx.x;
    const int lane = tid & 31;
    const int w    = tid >> 5;           // warp 0..15
    const int b    = blockIdx.y;
    const int i0   = blockIdx.x * BI;

    const int mwarp = w >> 2;            // 0..3  -> m base = mwarp*32
    const int nwarp = w & 3;             // 0..3  -> n base = nwarp*16

    // ldmatrix lane address offsets
    const int quad = lane >> 3, lr = lane & 7;
    const uint32_t aoff = (uint32_t)(((quad & 1) * 8 + lr) * APITCH + (quad >> 1) * 16);
    const uint32_t boff = (uint32_t)(((quad >> 1) * 8 + lr) * APITCH + (quad & 1) * 16);
    const uint32_t aAh = sbase + SA_H + (mwarp * 32) * APITCH + aoff;
    const uint32_t aAl = sbase + SA_L + (mwarp * 32) * APITCH + aoff;
    const uint32_t aBh = sbase + SB_H + (nwarp * 16) * APITCH + boff;
    const uint32_t aBl = sbase + SB_L + (nwarp * 16) * APITCH + boff;

    float acc[2][2][4];
#pragma unroll
    for (int i = 0; i < 2; ++i)
#pragma unroll
        for (int j = 0; j < 2; ++j)
#pragma unroll
            for (int k = 0; k < 4; ++k) acc[i][j][k] = 0.f;
    float psum[8];
#pragma unroll
    for (int i = 0; i < 8; ++i) psum[i] = 0.f;

    for (int jb = 0; jb < M_DIM / BJ; ++jb) {
        const int j0 = jb * BJ;

        // --- stage B split tiles (64 rows x 256B each) ---
#pragma unroll
        for (int it = 0; it < 2; ++it) {
            const int chunk = tid + it * 512;     // 0..1023
            const int rowb  = chunk >> 4;         // 0..63
            const int ch    = chunk & 15;
            const size_t gidx = ((size_t)b * F_OUT + rowb) * M_DIM + j0;
            const uint4 vh = ((const uint4*)(g_WhT_h + gidx))[ch];
            const uint4 vl = ((const uint4*)(g_WhT_l + gidx))[ch];
            *(uint4*)(smem + SB_H + rowb * APITCH + ch * 16) = vh;
            *(uint4*)(smem + SB_L + rowb * APITCH + ch * 16) = vl;
        }

        // --- stage 1: warp-per-row p scores -> split bf16 A tiles ---
        const float4 e2v  = *(const float4*)(g_E2  + (size_t)b * M_DIM + j0 + lane * 4);
        const float4 e2av = *(const float4*)(g_E2a + (size_t)b * M_DIM + j0 + lane * 4);
#pragma unroll
        for (int rr = 0; rr < 8; ++rr) {
            const int row = w * 8 + rr;
            const float rv = g_r[(size_t)b * M_DIM + i0 + row];
            const int4 av = *(const int4*)(adj
                + ((size_t)(b * M_DIM + i0 + row)) * M_DIM + j0 + lane * 4);
            float p0 = fmaxf(e2v.x, rv * e2av.x) * __int_as_float(av.x * 0x3F800000);
            float p1 = fmaxf(e2v.y, rv * e2av.y) * __int_as_float(av.y * 0x3F800000);
            float p2 = fmaxf(e2v.z, rv * e2av.z) * __int_as_float(av.z * 0x3F800000);
            float p3 = fmaxf(e2v.w, rv * e2av.w) * __int_as_float(av.w * 0x3F800000);
            psum[rr] += (p0 + p1) + (p2 + p3);
            const uint32_t h01 = pack_bf16(p0, p1);
            const uint32_t h23 = pack_bf16(p2, p3);
            const uint32_t l01 = pack_bf16(p0 - __uint_as_float(h01 << 16),
                                           p1 - __uint_as_float(h01 & 0xFFFF0000u));
            const uint32_t l23 = pack_bf16(p2 - __uint_as_float(h23 << 16),
                                           p3 - __uint_as_float(h23 & 0xFFFF0000u));
            *(uint2*)(smem + SA_H + row * APITCH + lane * 8) = make_uint2(h01, h23);
            *(uint2*)(smem + SA_L + row * APITCH + lane * 8) = make_uint2(l01, l23);
        }
        __syncthreads();

        // --- MMA loop: 8 k-steps, terms hh + hl + lh ---
#pragma unroll 1
        for (int kt = 0; kt < 8; ++kt) {
            const uint32_t ko = kt * 32;
            uint32_t ah0[4], ah1[4], bh[4], bl[4], al0[4], al1[4];
            ldsm4(ah0, aAh + ko);
            ldsm4(ah1, aAh + 16 * APITCH + ko);
            ldsm4(bh,  aBh + ko);
            mma_bf16(acc[0][0], ah0, bh[0], bh[1]);
            mma_bf16(acc[0][1], ah0, bh[2], bh[3]);
            mma_bf16(acc[1][0], ah1, bh[0], bh[1]);
            mma_bf16(acc[1][1], ah1, bh[2], bh[3]);
            ldsm4(bl, aBl + ko);
            mma_bf16(acc[0][0], ah0, bl[0], bl[1]);
            mma_bf16(acc[0][1], ah0, bl[2], bl[3]);
            mma_bf16(acc[1][0], ah1, bl[0], bl[1]);
            mma_bf16(acc[1][1], ah1, bl[2], bl[3]);
            ldsm4(al0, aAl + ko);
            ldsm4(al1, aAl + 16 * APITCH + ko);
            mma_bf16(acc[0][0], al0, bh[0], bh[1]);
            mma_bf16(acc[0][1], al0, bh[2], bh[3]);
            mma_bf16(acc[1][0], al1, bh[0], bh[1]);
            mma_bf16(acc[1][1], al1, bh[2], bh[3]);
        }
        __syncthreads();
    }

    // --- row sums: per-warp reduce (each row owned by exactly one warp) ---
#pragma unroll
    for (int rr = 0; rr < 8; ++rr) {
        float s = psum[rr];
        s += __shfl_xor_sync(0xffffffffu, s, 16);
        s += __shfl_xor_sync(0xffffffffu, s, 8);
        s += __shfl_xor_sync(0xffffffffu, s, 4);
        s += __shfl_xor_sync(0xffffffffu, s, 2);
        s += __shfl_xor_sync(0xffffffffu, s, 1);
        if (lane == 0) ls[w * 8 + rr] = s;
    }
    __syncthreads();

    // --- epilogue: normalize, ELU, store ---
    const size_t obase = ((size_t)b * M_DIM + i0) * F_OUT;
#pragma unroll
    for (int mt = 0; mt < 2; ++mt) {
        const int r0 = mwarp * 32 + mt * 16 + (lane >> 2);
        const float inv0 = 1.0f / ls[r0];
        const float inv1 = 1.0f / ls[r0 + 8];
#pragma unroll
        for (int nt = 0; nt < 2; ++nt) {
            const int col = nwarp * 16 + nt * 8 + 2 * (lane & 3);
            float x0 = acc[mt][nt][0] * inv0;
            float x1 = acc[mt][nt][1] * inv0;
            float x2 = acc[mt][nt][2] * inv1;
            float x3 = acc[mt][nt][3] * inv1;
            x0 = (x0 > 0.f) ? x0 : (expf(x0) - 1.f);
            x1 = (x1 > 0.f) ? x1 : (expf(x1) - 1.f);
            x2 = (x2 > 0.f) ? x2 : (expf(x2) - 1.f);
            x3 = (x3 > 0.f) ? x3 : (expf(x3) - 1.f);
            *(float2*)(out + obase + (size_t)r0 * F_OUT + col) = make_float2(x0, x1);
            *(float2*)(out + obase + (size_t)(r0 + 8) * F_OUT + col) = make_float2(x2, x3);
        }
    }
}

// ---------------------------------------------------------------------------
extern "C" void kernel_launch(void* const* d_in, const int* in_sizes, int n_in,
                              void* d_out, int out_size) {
    const float* h   = (const float*)d_in[0];
    const int*   adj = (const int*)d_in[1];
    const float* W   = (const float*)d_in[2];
    const float* a   = (const float*)d_in[3];
    float* out = (float*)d_out;
    (void)in_sizes; (void)n_in; (void)out_size;

    cudaFuncSetAttribute(k_gat, cudaFuncAttributeMaxDynamicSharedMemorySize,
                         SMEM_TOTAL);

    k_wh<<<(B_DIM * M_DIM) / 32, 512>>>(h, W, a);

    dim3 grid2(M_DIM / BI, B_DIM);
    k_gat<<<grid2, 512, SMEM_TOTAL>>>(adj, out);
}

// round 11
// speedup vs baseline: 3.1447x; 1.0512x over previous
#include <cuda_runtime.h>
#include <cuda_bf16.h>
#include <cstdint>

#define B_DIM 16
#define M_DIM 2048
#define F_IN  128
#define F_OUT 64
#define ALPHA 0.2f

// ---------------------------------------------------------------------------
// __device__ scratch (allocation-free rule)
// ---------------------------------------------------------------------------
__device__ float g_r  [(size_t)B_DIM * M_DIM];
__device__ float g_E2 [(size_t)B_DIM * M_DIM];
__device__ float g_E2a[(size_t)B_DIM * M_DIM];
// Wh transposed + bf16 2-term split: [B][F_OUT][M]  (hi + lo)
__device__ __nv_bfloat16 g_WhT_h[(size_t)B_DIM * F_OUT * M_DIM];
__device__ __nv_bfloat16 g_WhT_l[(size_t)B_DIM * F_OUT * M_DIM];

// ---------------------------------------------------------------------------
// helpers
// ---------------------------------------------------------------------------
__device__ __forceinline__ uint32_t smem_u32(const void* p) {
    uint32_t a;
    asm("{ .reg .u64 t; cvta.to.shared.u64 t, %1; cvt.u32.u64 %0, t; }"
        : "=r"(a) : "l"(p));
    return a;
}
// pack two f32 -> bf16x2 (lo 16 bits = a, hi 16 bits = b), round-to-nearest
__device__ __forceinline__ uint32_t pack_bf16(float a, float b) {
    uint32_t r;
    asm("cvt.rn.satfinite.bf16x2.f32 %0, %1, %2;" : "=r"(r) : "f"(b), "f"(a));
    return r;
}
__device__ __forceinline__ void ldsm4(uint32_t* r, uint32_t addr) {
    asm volatile("ldmatrix.sync.aligned.m8n8.x4.shared.b16 {%0,%1,%2,%3}, [%4];"
                 : "=r"(r[0]), "=r"(r[1]), "=r"(r[2]), "=r"(r[3]) : "r"(addr));
}
__device__ __forceinline__ void mma_bf16(float* d, const uint32_t* a,
                                         uint32_t b0, uint32_t b1) {
    asm volatile(
        "mma.sync.aligned.m16n8k16.row.col.f32.bf16.bf16.f32 "
        "{%0,%1,%2,%3}, {%4,%5,%6,%7}, {%8,%9}, {%0,%1,%2,%3};"
        : "+f"(d[0]), "+f"(d[1]), "+f"(d[2]), "+f"(d[3])
        : "r"(a[0]), "r"(a[1]), "r"(a[2]), "r"(a[3]), "r"(b0), "r"(b1));
}

// ---------------------------------------------------------------------------
// Kernel 1: Wh = h @ W ; f1/f2 dots ; separable-exp precomputes ;
// Wh transposed + rn bf16 split -> g_WhT_h / g_WhT_l.
// v3: 64 rows per 512-thread CTA (256 CTAs), dynamic smem.
// ---------------------------------------------------------------------------
#define WH_WS   0               // 8192 f32 = 32768 B
#define WH_HS   32768           // 64 x 128 f32 = 32768 B
#define WH_WHS  65536           // 64 x 68 f32 = 17408 B
#define WH_SMEM 82944

__global__ __launch_bounds__(512) void k_wh(const float* __restrict__ h,
                                            const float* __restrict__ W,
                                            const float* __restrict__ a) {
    extern __shared__ char wsm[];
    float* Ws  = (float*)(wsm + WH_WS);
    float* hs  = (float*)(wsm + WH_HS);    // [64][128]
    float* whs = (float*)(wsm + WH_WHS);   // [64][68]
    const int tid = threadIdx.x;
    const size_t row0 = (size_t)blockIdx.x * 64;
    const int b_    = (int)(row0 >> 11);
    const int jbase = (int)(row0 & 2047);

    {
        const float4* ws = (const float4*)W;
        float4* wd = (float4*)Ws;
#pragma unroll
        for (int k = 0; k < 4; ++k) wd[tid + 512 * k] = ws[tid + 512 * k];
        const float4* hsrc = (const float4*)(h + row0 * F_IN);
        float4* hdst = (float4*)hs;
#pragma unroll
        for (int k = 0; k < 4; ++k) hdst[tid + 512 * k] = hsrc[tid + 512 * k];
    }
    __syncthreads();

    const int c  = tid & 63;
    const int r0 = tid >> 6;             // rows r0 + 8u, u = 0..7
    float acc[8];
#pragma unroll
    for (int u = 0; u < 8; ++u) acc[u] = 0.f;
#pragma unroll 4
    for (int k = 0; k < F_IN; ++k) {
        const float wv = Ws[k * F_OUT + c];
#pragma unroll
        for (int u = 0; u < 8; ++u)
            acc[u] += hs[(r0 + 8 * u) * F_IN + k] * wv;
    }
#pragma unroll
    for (int u = 0; u < 8; ++u)
        whs[(r0 + 8 * u) * 68 + c] = acc[u];
    __syncthreads();

    // transposed bf16 split store: thread -> col cc = tid>>3, 8 rows at (tid&7)*8
    {
        const int cc = tid >> 3;
        const int rq = tid & 7;
        float x[8];
#pragma unroll
        for (int u = 0; u < 8; ++u) x[u] = whs[(rq * 8 + u) * 68 + cc];
        uint32_t hh[4], ll[4];
#pragma unroll
        for (int q = 0; q < 4; ++q) {
            hh[q] = pack_bf16(x[2 * q], x[2 * q + 1]);
            const float l0 = x[2 * q]     - __uint_as_float(hh[q] << 16);
            const float l1 = x[2 * q + 1] - __uint_as_float(hh[q] & 0xFFFF0000u);
            ll[q] = pack_bf16(l0, l1);
        }
        const size_t idx = ((size_t)b_ * F_OUT + cc) * M_DIM + jbase + rq * 8;
        *(uint4*)(g_WhT_h + idx) = make_uint4(hh[0], hh[1], hh[2], hh[3]);
        *(uint4*)(g_WhT_l + idx) = make_uint4(ll[0], ll[1], ll[2], ll[3]);
    }

    // f1/f2 per row: 128 threads, each one (row, which) dot of length 64
    if (tid < 128) {
        const int row   = tid >> 1;
        const int which = tid & 1;
        float f = 0.f;
#pragma unroll 8
        for (int k = 0; k < F_OUT; ++k)
            f += whs[row * 68 + k] * a[which * F_OUT + k];
        const size_t grow = row0 + row;
        if (which == 0) {
            g_r[grow] = expf((ALPHA - 1.0f) * f);
        } else {
            g_E2[grow]  = expf(f);
            g_E2a[grow] = expf(ALPHA * f);
        }
    }
}

// ---------------------------------------------------------------------------
// Kernel 2: fused masked-softmax + attn@Wh (mma.sync bf16-split) + elu.
// Grid (16,16): CTA = 128 rows x batch. 512 threads = 16 warps (4m x 4n,
// warp tile 32x16). occ 2 -> one wave.
// jb sweep STAGGERED per CTA so co-resident CTAs anti-phase their
// stage (L1/DRAM-heavy) and MMA (tensor-heavy) phases.
// ---------------------------------------------------------------------------
#define BI 128
#define BJ 128
#define APITCH 272               // bytes per tile row (136 bf16, 17 x 16B)
#define SA_H 0                   // 128 x 272 = 34816
#define SA_L 34816
#define SB_H 69632               // 64 x 272 = 17408
#define SB_L 87040
#define SRS  104448              // 128 f32 r values
#define SLS  104960              // 128 f32 row sums
#define SMEM_TOTAL 105472

__global__ __launch_bounds__(512, 2) void k_gat(const int* __restrict__ adj,
                                                float* __restrict__ out) {
    extern __shared__ char smem[];
    const uint32_t sbase = smem_u32(smem);
    float* rsm = (float*)(smem + SRS);
    float* ls  = (float*)(smem + SLS);

    const int tid  = threadIdx.x;
    const int lane = tid & 31;
    const int w    = tid >> 5;           // warp 0..15
    const int b    = blockIdx.y;
    const int i0   = blockIdx.x * BI;

    const int mwarp = w >> 2;            // 0..3  -> m base = mwarp*32
    const int nwarp = w & 3;             // 0..3  -> n base = nwarp*16

    // stage r values once
    if (tid < 128) rsm[tid] = g_r[(size_t)b * M_DIM + i0 + tid];

    // ldmatrix lane address offsets
    const int quad = lane >> 3, lr = lane & 7;
    const uint32_t aoff = (uint32_t)(((quad & 1) * 8 + lr) * APITCH + (quad >> 1) * 16);
    const uint32_t boff = (uint32_t)(((quad >> 1) * 8 + lr) * APITCH + (quad & 1) * 16);
    const uint32_t aAh = sbase + SA_H + (mwarp * 32) * APITCH + aoff;
    const uint32_t aAl = sbase + SA_L + (mwarp * 32) * APITCH + aoff;
    const uint32_t aBh = sbase + SB_H + (nwarp * 16) * APITCH + boff;
    const uint32_t aBl = sbase + SB_L + (nwarp * 16) * APITCH + boff;

    float acc[2][2][4];
#pragma unroll
    for (int i = 0; i < 2; ++i)
#pragma unroll
        for (int j = 0; j < 2; ++j)
#pragma unroll
            for (int k = 0; k < 4; ++k) acc[i][j][k] = 0.f;
    float psum[8];
#pragma unroll
    for (int i = 0; i < 8; ++i) psum[i] = 0.f;

    // per-CTA phase stagger (co-resident CTAs anti-phase)
    const int jb0 = (2 * blockIdx.x + blockIdx.y) & 15;
    __syncthreads();   // rsm visible

    for (int jbi = 0; jbi < M_DIM / BJ; ++jbi) {
        const int jb = (jbi + jb0) & 15;
        const int j0 = jb * BJ;

        // --- stage B split tiles (64 rows x 256B each) ---
#pragma unroll
        for (int it = 0; it < 2; ++it) {
            const int chunk = tid + it * 512;     // 0..1023
            const int rowb  = chunk >> 4;         // 0..63
            const int ch    = chunk & 15;
            const size_t gidx = ((size_t)b * F_OUT + rowb) * M_DIM + j0;
            const uint4 vh = ((const uint4*)(g_WhT_h + gidx))[ch];
            const uint4 vl = ((const uint4*)(g_WhT_l + gidx))[ch];
            *(uint4*)(smem + SB_H + rowb * APITCH + ch * 16) = vh;
            *(uint4*)(smem + SB_L + rowb * APITCH + ch * 16) = vl;
        }

        // --- stage 1: warp-per-row p scores -> split bf16 A tiles ---
        const float4 e2v  = *(const float4*)(g_E2  + (size_t)b * M_DIM + j0 + lane * 4);
        const float4 e2av = *(const float4*)(g_E2a + (size_t)b * M_DIM + j0 + lane * 4);
#pragma unroll
        for (int rr = 0; rr < 8; ++rr) {
            const int row = w * 8 + rr;
            const float rv = rsm[row];
            const int4 av = *(const int4*)(adj
                + ((size_t)(b * M_DIM + i0 + row)) * M_DIM + j0 + lane * 4);
            float p0 = fmaxf(e2v.x, rv * e2av.x) * __int_as_float(av.x * 0x3F800000);
            float p1 = fmaxf(e2v.y, rv * e2av.y) * __int_as_float(av.y * 0x3F800000);
            float p2 = fmaxf(e2v.z, rv * e2av.z) * __int_as_float(av.z * 0x3F800000);
            float p3 = fmaxf(e2v.w, rv * e2av.w) * __int_as_float(av.w * 0x3F800000);
            psum[rr] += (p0 + p1) + (p2 + p3);
            const uint32_t h01 = pack_bf16(p0, p1);
            const uint32_t h23 = pack_bf16(p2, p3);
            const uint32_t l01 = pack_bf16(p0 - __uint_as_float(h01 << 16),
                                           p1 - __uint_as_float(h01 & 0xFFFF0000u));
            const uint32_t l23 = pack_bf16(p2 - __uint_as_float(h23 << 16),
                                           p3 - __uint_as_float(h23 & 0xFFFF0000u));
            *(uint2*)(smem + SA_H + row * APITCH + lane * 8) = make_uint2(h01, h23);
            *(uint2*)(smem + SA_L + row * APITCH + lane * 8) = make_uint2(l01, l23);
        }
        __syncthreads();

        // --- MMA loop: 8 k-steps, terms hh + hl + lh ---
#pragma unroll 1
        for (int kt = 0; kt < 8; ++kt) {
            const uint32_t ko = kt * 32;
            uint32_t ah0[4], ah1[4], bh[4], bl[4], al0[4], al1[4];
            ldsm4(ah0, aAh + ko);
            ldsm4(ah1, aAh + 16 * APITCH + ko);
            ldsm4(bh,  aBh + ko);
            mma_bf16(acc[0][0], ah0, bh[0], bh[1]);
            mma_bf16(acc[0][1], ah0, bh[2], bh[3]);
            mma_bf16(acc[1][0], ah1, bh[0], bh[1]);
            mma_bf16(acc[1][1], ah1, bh[2], bh[3]);
            ldsm4(bl, aBl + ko);
            mma_bf16(acc[0][0], ah0, bl[0], bl[1]);
            mma_bf16(acc[0][1], ah0, bl[2], bl[3]);
            mma_bf16(acc[1][0], ah1, bl[0], bl[1]);
            mma_bf16(acc[1][1], ah1, bl[2], bl[3]);
            ldsm4(al0, aAl + ko);
            ldsm4(al1, aAl + 16 * APITCH + ko);
            mma_bf16(acc[0][0], al0, bh[0], bh[1]);
            mma_bf16(acc[0][1], al0, bh[2], bh[3]);
            mma_bf16(acc[1][0], al1, bh[0], bh[1]);
            mma_bf16(acc[1][1], al1, bh[2], bh[3]);
        }
        __syncthreads();
    }

    // --- row sums: per-warp reduce (each row owned by exactly one warp) ---
#pragma unroll
    for (int rr = 0; rr < 8; ++rr) {
        float s = psum[rr];
        s += __shfl_xor_sync(0xffffffffu, s, 16);
        s += __shfl_xor_sync(0xffffffffu, s, 8);
        s += __shfl_xor_sync(0xffffffffu, s, 4);
        s += __shfl_xor_sync(0xffffffffu, s, 2);
        s += __shfl_xor_sync(0xffffffffu, s, 1);
        if (lane == 0) ls[w * 8 + rr] = s;
    }
    __syncthreads();

    // --- epilogue: normalize, ELU, store ---
    const size_t obase = ((size_t)b * M_DIM + i0) * F_OUT;
#pragma unroll
    for (int mt = 0; mt < 2; ++mt) {
        const int r0 = mwarp * 32 + mt * 16 + (lane >> 2);
        const float inv0 = 1.0f / ls[r0];
        const float inv1 = 1.0f / ls[r0 + 8];
#pragma unroll
        for (int nt = 0; nt < 2; ++nt) {
            const int col = nwarp * 16 + nt * 8 + 2 * (lane & 3);
            float x0 = acc[mt][nt][0] * inv0;
            float x1 = acc[mt][nt][1] * inv0;
            float x2 = acc[mt][nt][2] * inv1;
            float x3 = acc[mt][nt][3] * inv1;
            x0 = (x0 > 0.f) ? x0 : (expf(x0) - 1.f);
            x1 = (x1 > 0.f) ? x1 : (expf(x1) - 1.f);
            x2 = (x2 > 0.f) ? x2 : (expf(x2) - 1.f);
            x3 = (x3 > 0.f) ? x3 : (expf(x3) - 1.f);
            *(float2*)(out + obase + (size_t)r0 * F_OUT + col) = make_float2(x0, x1);
            *(float2*)(out + obase + (size_t)(r0 + 8) * F_OUT + col) = make_float2(x2, x3);
        }
    }
}

// ---------------------------------------------------------------------------
extern "C" void kernel_launch(void* const* d_in, const int* in_sizes, int n_in,
                              void* d_out, int out_size) {
    const float* h   = (const float*)d_in[0];
    const int*   adj = (const int*)d_in[1];
    const float* W   = (const float*)d_in[2];
    const float* a   = (const float*)d_in[3];
    float* out = (float*)d_out;
    (void)in_sizes; (void)n_in; (void)out_size;

    cudaFuncSetAttribute(k_wh, cudaFuncAttributeMaxDynamicSharedMemorySize,
                         WH_SMEM);
    cudaFuncSetAttribute(k_gat, cudaFuncAttributeMaxDynamicSharedMemorySize,
                         SMEM_TOTAL);

    k_wh<<<(B_DIM * M_DIM) / 64, 512, WH_SMEM>>>(h, W, a);

    dim3 grid2(M_DIM / BI, B_DIM);
    k_gat<<<grid2, 512, SMEM_TOTAL>>>(adj, out);
}